// round 13
// baseline (speedup 1.0000x reference)
#include <cuda_runtime.h>
#include <math.h>
#include <stdint.h>

// Problem dims
#define B_   1024
#define Z_   256
#define TD_  512
#define CF_  1024
#define A_   64
#define R_   128
#define T_   64
#define G_   4096   // 4*CF

// Output layout: acts [B,T,A] | ts [B,T] | ress [B,T,R]
#define TS_BASE   (B_*T_*A_)
#define RESS_BASE (TS_BASE + B_*T_)

#define NT 512     // threads per CTA

// ---------------- scratch (device globals) -----------------------------------
__device__ float g_trec[B_*TD_];
__device__ float g_Pa[B_*G_];      // interleaved: P[m][j*4+g]
__device__ float g_Pr[B_*G_];
__device__ float g_Pt[B_*G_];
__device__ float g_hA[B_*CF_];     // plain h (act head)
__device__ float g_hR[B_*CF_];     // plain h (res head)
__device__ float g_cA[B_*CF_];
__device__ float g_cR[B_*CF_];
__device__ float g_cT[B_*CF_];
__device__ float g_hidden[B_*(CF_/2)];
// pre-split tf32 hi/lo A operands in m16n8k8 fragment layout (ping-pong)
__device__ float g_AhA[2][B_*CF_], g_AlA[2][B_*CF_];
__device__ float g_AhR[2][B_*CF_], g_AlR[2][B_*CF_];
__device__ float g_AhT[2][B_*CF_], g_AlT[2][B_*CF_];
// B operands: hi/lo INTERLEAVED per lane (uint4 = {hi0,hi1,lo0,lo1}) -> 1 LDG.128
__device__ float g_BcA[2*G_*CF_];   // Whh_a (gate-interleaved cols)
__device__ float g_BcR[2*G_*CF_];
__device__ float g_BcT[2*G_*CF_];
__device__ float g_Bw1c[CF_*CF_];   // e2ts_w1 (CF/2 cols x CF k x 2)
// one-hot column tables (interleaved per row: [idx][j*4+g])
__device__ float g_WaA[A_*G_];
__device__ float g_WaR[A_*G_];
__device__ float g_WrR[R_*G_];
__device__ float g_WaT[A_*G_];
__device__ float g_WtT[G_];
__device__ int   g_actidx[B_];
__device__ int   g_residx[B_];
__device__ float g_tsv[B_];

__device__ unsigned g_bar_count = 0;
__device__ unsigned g_bar_gen   = 0;
__device__ unsigned g_done      = 0;   // phase-B light-item completion counter

// ---------------- software grid barrier --------------------------------------
__device__ __forceinline__ void grid_sync() {
    __syncthreads();
    if (threadIdx.x == 0) {
        __threadfence();
        unsigned gen = *(volatile unsigned*)&g_bar_gen;
        if (atomicAdd(&g_bar_count, 1u) == gridDim.x - 1) {
            g_bar_count = 0;
            __threadfence();
            atomicAdd(&g_bar_gen, 1u);
        } else {
            while (*(volatile unsigned*)&g_bar_gen == gen) __nanosleep(64);
        }
        __threadfence();
    }
    __syncthreads();
}

// ---------------- tf32 helpers ------------------------------------------------
__device__ __forceinline__ uint32_t f2tf(float x) {
    uint32_t u;
    asm("cvt.rna.tf32.f32 %0, %1;" : "=r"(u) : "f"(x));
    return u;
}

__device__ __forceinline__ void mma8(float* c, const uint32_t* a, const uint32_t* b) {
    asm volatile(
        "mma.sync.aligned.m16n8k8.row.col.f32.tf32.tf32.f32 "
        "{%0,%1,%2,%3}, {%4,%5,%6,%7}, {%8,%9}, {%0,%1,%2,%3};"
        : "+f"(c[0]), "+f"(c[1]), "+f"(c[2]), "+f"(c[3])
        : "r"(a[0]), "r"(a[1]), "r"(a[2]), "r"(a[3]), "r"(b[0]), "r"(b[1]));
}

// A-frag split-store: element (m, k) of an A operand [1024 x 1024]
__device__ __forceinline__ void store_Asplit(float* Ah, float* Al, int m, int k, float v) {
    int r = m & 15;
    int lane = (r & 7) * 4 + (k & 3);
    int reg  = (r >> 3) + 2 * ((k >> 2) & 1);
    size_t off = (((size_t)((m >> 4) * 128 + (k >> 3)) * 32 + lane) * 4 + reg);
    float hi = __uint_as_float(f2tf(v));
    Ah[off] = hi;
    Al[off] = __uint_as_float(f2tf(v - hi));
}

// B-frag combined split-store: output col cg, k (0..1023).
__device__ __forceinline__ void store_Bsplit(float* Bc, int cg, int k, float v) {
    int lanei = (cg & 7) * 4 + (k & 3);
    int reg   = (k >> 2) & 1;
    size_t off = ((size_t)((cg >> 3) * 128 + (k >> 3)) * 128) + lanei * 4 + reg;
    float hi = __uint_as_float(f2tf(v));
    Bc[off]     = hi;
    Bc[off + 2] = __uint_as_float(f2tf(v - hi));
}

__device__ __forceinline__ float sigm(float x) { return 1.f / (1.f + expf(-x)); }

// ---------------- direct-LDG 3xTF32 mma tile (512 threads) -------------------
// C[128x128] += A@B^T, K=1024. Warp grid 4x4, each warp 32x32 output.
// mode 1: bias+relu store stride 512 (ts hidden).
// mode 2: fused a-cell  (P + Wa[actidx])
// mode 3: fused r-cell  (P + Wa[actidx] + Wr[residx])          [spins on g_done]
// mode 4: fused t-cell  (P + Wa[actidx] + tsv*Wt)              [spins on g_done]
__device__ void mma_direct(const float* __restrict__ Ah, const float* __restrict__ Al,
                           const float* __restrict__ Bc,
                           int tm, int tn, int mode,
                           float* __restrict__ Gout, const float* __restrict__ bias,
                           const float* __restrict__ Ppre, const float* __restrict__ Wtab,
                           const float* __restrict__ Wtab2, const int* __restrict__ idx2,
                           const float* __restrict__ wtp, const float* __restrict__ tsvp,
                           const int* __restrict__ actidx, float* __restrict__ cbuf,
                           float* __restrict__ hplain,
                           float* __restrict__ Ahout, float* __restrict__ Alout,
                           unsigned done_target)
{
    const int tid  = threadIdx.x;
    const int lane = tid & 31;
    const int warp = tid >> 5;            // 0..15
    const int wm = warp >> 2, wn = warp & 3;

    const uint4* A4h = (const uint4*)Ah;
    const uint4* A4l = (const uint4*)Al;
    const uint4* B4  = (const uint4*)Bc;

    int aidx[2], bidx[4];
    #pragma unroll
    for (int m = 0; m < 2; m++)
        aidx[m] = (tm * 8 + wm * 2 + m) * 4096 + lane;   // uint4 units, +k8*32
    #pragma unroll
    for (int n = 0; n < 4; n++)
        bidx[n] = (tn * 16 + wn * 4 + n) * 4096 + lane;  // uint4 units, +k8*32

    float acc[2][4][4];
    #pragma unroll
    for (int m = 0; m < 2; m++)
        #pragma unroll
        for (int n = 0; n < 4; n++)
            #pragma unroll
            for (int q = 0; q < 4; q++) acc[m][n][q] = 0.f;

    uint4 ah0[2], al0[2], ah1[2], al1[2];
    uint4 bc0[4], bc1[4];

    #pragma unroll
    for (int m = 0; m < 2; m++) { ah0[m] = A4h[aidx[m]]; al0[m] = A4l[aidx[m]]; }
    #pragma unroll
    for (int n = 0; n < 4; n++) bc0[n] = B4[bidx[n]];

    for (int k8 = 0; k8 < 128; k8 += 2) {
        #pragma unroll
        for (int m = 0; m < 2; m++) {
            int o = aidx[m] + (k8 + 1) * 32;
            ah1[m] = A4h[o]; al1[m] = A4l[o];
        }
        #pragma unroll
        for (int n = 0; n < 4; n++)
            bc1[n] = B4[bidx[n] + (k8 + 1) * 32];
        #pragma unroll
        for (int m = 0; m < 2; m++)
            #pragma unroll
            for (int n = 0; n < 4; n++) {
                mma8(acc[m][n], (const uint32_t*)&ah0[m], (const uint32_t*)&bc0[n].x);
                mma8(acc[m][n], (const uint32_t*)&ah0[m], (const uint32_t*)&bc0[n].z);
                mma8(acc[m][n], (const uint32_t*)&al0[m], (const uint32_t*)&bc0[n].x);
            }
        if (k8 + 2 < 128) {
            #pragma unroll
            for (int m = 0; m < 2; m++) {
                int o = aidx[m] + (k8 + 2) * 32;
                ah0[m] = A4h[o]; al0[m] = A4l[o];
            }
            #pragma unroll
            for (int n = 0; n < 4; n++)
                bc0[n] = B4[bidx[n] + (k8 + 2) * 32];
        }
        #pragma unroll
        for (int m = 0; m < 2; m++)
            #pragma unroll
            for (int n = 0; n < 4; n++) {
                mma8(acc[m][n], (const uint32_t*)&ah1[m], (const uint32_t*)&bc1[n].x);
                mma8(acc[m][n], (const uint32_t*)&ah1[m], (const uint32_t*)&bc1[n].z);
                mma8(acc[m][n], (const uint32_t*)&al1[m], (const uint32_t*)&bc1[n].x);
            }
    }

    // ---- epilogue ----
    if (mode == 1) {
        #pragma unroll
        for (int m = 0; m < 2; m++) {
            int r1 = tm * 128 + wm * 32 + m * 16 + (lane >> 2);
            #pragma unroll
            for (int n = 0; n < 4; n++) {
                int cg = tn * 128 + wn * 32 + n * 8 + (lane & 3) * 2;
                float v0 = fmaxf(acc[m][n][0] + bias[cg],     0.f);
                float v1 = fmaxf(acc[m][n][1] + bias[cg + 1], 0.f);
                float v2 = fmaxf(acc[m][n][2] + bias[cg],     0.f);
                float v3 = fmaxf(acc[m][n][3] + bias[cg + 1], 0.f);
                *(float2*)&Gout[(size_t)r1 * (CF_/2) + cg]       = make_float2(v0, v1);
                *(float2*)&Gout[(size_t)(r1 + 8) * (CF_/2) + cg] = make_float2(v2, v3);
            }
        }
        return;
    }

    // modes 2/3/4: fused LSTM cell epilogue
    if (mode >= 3) {
        // wait for this step's act-head / ts-dot items (producers fence+add)
        if (tid == 0) {
            while (*(volatile unsigned*)&g_done < done_target) __nanosleep(64);
            __threadfence();
        }
        __syncthreads();
    }

    const bool low = ((lane & 1) == 0);
    #pragma unroll
    for (int m = 0; m < 2; m++) {
        int r1 = tm * 128 + wm * 32 + m * 16 + (lane >> 2);
        #pragma unroll
        for (int n = 0; n < 4; n++) {
            int cg = tn * 128 + wn * 32 + n * 8 + (lane & 3) * 2;
            int j  = cg >> 2;
            float o0 = acc[m][n][0], o1 = acc[m][n][1];
            float o2 = acc[m][n][2], o3 = acc[m][n][3];
            float p0 = __shfl_xor_sync(0xffffffffu, o0, 1);
            float p1 = __shfl_xor_sync(0xffffffffu, o1, 1);
            float p2 = __shfl_xor_sync(0xffffffffu, o2, 1);
            float p3 = __shfl_xor_sync(0xffffffffu, o3, 1);
            if (low) {
                #pragma unroll
                for (int rr2 = 0; rr2 < 2; rr2++) {
                    int row = r1 + rr2 * 8;
                    float oi = rr2 ? o2 : o0;
                    float of = rr2 ? o3 : o1;
                    float og = rr2 ? p2 : p0;
                    float oo = rr2 ? p3 : p1;
                    int ai = actidx[row];
                    float2 pA = *(const float2*)&Ppre[(size_t)row * G_ + j*4];
                    float2 pB = *(const float2*)&Ppre[(size_t)row * G_ + j*4 + 2];
                    float2 wA = *(const float2*)&Wtab[(size_t)ai * G_ + j*4];
                    float2 wB = *(const float2*)&Wtab[(size_t)ai * G_ + j*4 + 2];
                    float gi = oi + pA.x + wA.x;
                    float gf = of + pA.y + wA.y;
                    float gg = og + pB.x + wB.x;
                    float go = oo + pB.y + wB.y;
                    if (mode == 3) {
                        int ri = idx2[row];
                        float2 rA = *(const float2*)&Wtab2[(size_t)ri * G_ + j*4];
                        float2 rB = *(const float2*)&Wtab2[(size_t)ri * G_ + j*4 + 2];
                        gi += rA.x; gf += rA.y; gg += rB.x; go += rB.y;
                    } else if (mode == 4) {
                        float tv = tsvp[row];
                        float2 tA = *(const float2*)&wtp[j*4];
                        float2 tB = *(const float2*)&wtp[j*4 + 2];
                        gi += tv * tA.x; gf += tv * tA.y;
                        gg += tv * tB.x; go += tv * tB.y;
                    }
                    size_t off = (size_t)row * CF_ + j;
                    float cn = sigm(gf) * cbuf[off] + sigm(gi) * tanhf(gg);
                    cbuf[off] = cn;
                    float hv = sigm(go) * tanhf(cn);
                    if (mode != 4) hplain[off] = hv;
                    store_Asplit(Ahout, Alout, row, j, hv);
                }
            }
        }
    }
}

// ---------------- res head block: 16 rows x 128 cols, writes out + residx ----
__device__ void res_head_block(int blk, int tcol,
                               const float* __restrict__ e2res_w,
                               const float* __restrict__ e2res_b,
                               float* __restrict__ out,
                               float* sA, float* sB)
{
    const int tid = threadIdx.x;
    int m0 = blk * 16;
    float acc4[4] = {0.f, 0.f, 0.f, 0.f};
    const float* h = g_hR;
    const int rr = tid >> 5, cc0 = (tid & 31) * 4;
    for (int kb = 0; kb < CF_; kb += 32) {
        if (tid < 128) {
            int r = tid >> 3, c4 = (tid & 7) * 4;
            float4 v = *(const float4*)&h[(size_t)(m0 + r) * CF_ + kb + c4];
            sA[r*32 + c4+0] = v.x; sA[r*32 + c4+1] = v.y;
            sA[r*32 + c4+2] = v.z; sA[r*32 + c4+3] = v.w;
        }
        #pragma unroll
        for (int qq = 0; qq < 2; qq++) {
            int idx = tid * 2 + qq;            // 1024 float4s
            int ccw = idx >> 3, k4 = (idx & 7) * 4;
            float4 v = *(const float4*)&e2res_w[(size_t)ccw * CF_ + kb + k4];
            sB[(k4+0)*128 + ccw] = v.x; sB[(k4+1)*128 + ccw] = v.y;
            sB[(k4+2)*128 + ccw] = v.z; sB[(k4+3)*128 + ccw] = v.w;
        }
        __syncthreads();
        #pragma unroll
        for (int k = 0; k < 32; k++) {
            float a = sA[rr*32 + k];
            acc4[0] += a * sB[k*128 + cc0];
            acc4[1] += a * sB[k*128 + cc0 + 1];
            acc4[2] += a * sB[k*128 + cc0 + 2];
            acc4[3] += a * sB[k*128 + cc0 + 3];
        }
        __syncthreads();
    }
    #pragma unroll
    for (int j = 0; j < 4; j++) {
        float v = acc4[j] + e2res_b[cc0 + j];
        sA[rr*128 + cc0 + j] = v;
        out[RESS_BASE + (size_t)(m0 + rr) * (T_*R_) + tcol*R_ + cc0 + j] = v;
    }
    __syncthreads();
    if (tid < 16) {
        float bv = -INFINITY; int bi = 0;
        for (int n = 0; n < R_; n++) {
            float v = sA[tid*128 + n];
            if (v > bv) { bv = v; bi = n; }
        }
        g_residx[m0 + tid] = bi;
    }
    __syncthreads();
}

// ---------------- fp32 SIMT 128x128 tile, 512 threads (setup GEMMs only) -----
__device__ __forceinline__ void gemm128(
    const float* __restrict__ A, int lda,
    const float* __restrict__ B, int ldb,
    int K, int bm, int bn,
    float* sA, float* sB, float acc[4][8])
{
    const int tid  = threadIdx.x;
    const int tx   = tid & 15, ty = tid >> 4;   // ty 0..31
    const int lrow = tid >> 2;                  // 0..127
    const int lseg = tid & 3;
    const bool bvec = ((ldb & 3) == 0);

    for (int kb = 0; kb < K; kb += 16) {
        {
            float4 v = *(const float4*)&A[(size_t)(bm + lrow) * lda + kb + lseg * 4];
            sA[(lseg*4+0)*128 + lrow] = v.x; sA[(lseg*4+1)*128 + lrow] = v.y;
            sA[(lseg*4+2)*128 + lrow] = v.z; sA[(lseg*4+3)*128 + lrow] = v.w;
        }
        {
            const float* bp = &B[(size_t)(bn + lrow) * ldb + kb + lseg * 4];
            float4 v;
            if (bvec) v = *(const float4*)bp;
            else { v.x = bp[0]; v.y = bp[1]; v.z = bp[2]; v.w = bp[3]; }
            sB[(lseg*4+0)*128 + lrow] = v.x; sB[(lseg*4+1)*128 + lrow] = v.y;
            sB[(lseg*4+2)*128 + lrow] = v.z; sB[(lseg*4+3)*128 + lrow] = v.w;
        }
        __syncthreads();
        #pragma unroll
        for (int k = 0; k < 16; k++) {
            float a[4], b[8];
            *(float4*)&a[0] = *(const float4*)&sA[k*128 + ty*4];
            *(float4*)&b[0] = *(const float4*)&sB[k*128 + tx*8];
            *(float4*)&b[4] = *(const float4*)&sB[k*128 + tx*8 + 4];
            #pragma unroll
            for (int i = 0; i < 4; i++)
                #pragma unroll
                for (int j = 0; j < 8; j++)
                    acc[i][j] += a[i] * b[j];
        }
        __syncthreads();
    }
}

// ---------------- the whole decoder as ONE persistent kernel -----------------
__global__ __launch_bounds__(NT, 1) void decoder_all(
    const float* __restrict__ z,
    const float* __restrict__ z2t_w, const float* __restrict__ z2t_b,
    const float* __restrict__ Wih_a, const float* __restrict__ Whh_a, const float* __restrict__ b_a,
    const float* __restrict__ Wih_r, const float* __restrict__ Whh_r, const float* __restrict__ b_r,
    const float* __restrict__ Wih_t, const float* __restrict__ Whh_t, const float* __restrict__ b_t,
    const float* __restrict__ e2act_w, const float* __restrict__ e2act_b,
    const float* __restrict__ e2res_w, const float* __restrict__ e2res_b,
    const float* __restrict__ e2ts_w1, const float* __restrict__ e2ts_b1,
    const float* __restrict__ e2ts_w2, const float* __restrict__ e2ts_b2,
    float* __restrict__ out)
{
    __shared__ float sA[2048];
    __shared__ float sB[4096];
    const int tid = threadIdx.x;
    const int bid = blockIdx.x;
    const int nb  = gridDim.x;
    const int nthr = nb * NT;
    const int gthr = bid * NT + tid;
    const int lane = tid & 31;
    const int wid  = tid >> 5;           // 0..15

    // ================= setup phase S0 =================
    if (gthr == 0) g_done = 0;           // reset handshake counter per launch
    for (int i = gthr; i < B_*CF_; i += nthr) {
        g_hA[i] = 0.f; g_cA[i] = 0.f;
        g_hR[i] = 0.f; g_cR[i] = 0.f;
        g_cT[i] = 0.f;
        g_AhA[0][i] = 0.f; g_AlA[0][i] = 0.f;
        g_AhA[1][i] = 0.f; g_AlA[1][i] = 0.f;
        g_AhR[0][i] = 0.f; g_AlR[0][i] = 0.f;
        g_AhR[1][i] = 0.f; g_AlR[1][i] = 0.f;
        g_AhT[0][i] = 0.f; g_AlT[0][i] = 0.f;
        g_AhT[1][i] = 0.f; g_AlT[1][i] = 0.f;
    }
    for (int i = gthr; i < B_; i += nthr) {
        g_actidx[i] = A_ - 1; g_residx[i] = R_ - 1; g_tsv[i] = 0.f;
    }
    // one-hot column tables (interleaved per row: [idx][j*4+g])
    for (int i = gthr; i < A_*G_; i += nthr) {
        int a = i >> 12, qy = i & 4095, j = qy >> 2, g = qy & 3;
        g_WaA[i] = Wih_a[(size_t)(g*CF_ + j) * (TD_+A_)      + TD_ + a];
        g_WaR[i] = Wih_r[(size_t)(g*CF_ + j) * (TD_+A_+R_)   + TD_ + a];
        g_WaT[i] = Wih_t[(size_t)(g*CF_ + j) * (TD_+A_+1)    + TD_ + a];
    }
    for (int i = gthr; i < R_*G_; i += nthr) {
        int r = i >> 12, qy = i & 4095, j = qy >> 2, g = qy & 3;
        g_WrR[i] = Wih_r[(size_t)(g*CF_ + j) * (TD_+A_+R_) + TD_ + A_ + r];
    }
    for (int i = gthr; i < G_; i += nthr) {
        int j = i >> 2, g = i & 3;
        g_WtT[i] = Wih_t[(size_t)(g*CF_ + j) * (TD_+A_+1) + TD_ + A_];
    }
    // Whh pre-split into combined fragment layout (gate-interleaved col order)
    for (int i = gthr; i < 3*G_*CF_; i += nthr) {
        int s  = i >> 22;
        int r  = i & (G_*CF_ - 1);
        int cg = r >> 10, k = r & 1023;
        int j = cg >> 2, g = cg & 3;
        const float* W = (s == 0) ? Whh_a : (s == 1) ? Whh_r : Whh_t;
        float* Bc = (s == 0) ? g_BcA : (s == 1) ? g_BcR : g_BcT;
        store_Bsplit(Bc, cg, k, W[(size_t)(g*CF_ + j) * CF_ + k]);
    }
    // e2ts_w1 pre-split (identity col order)
    for (int i = gthr; i < (CF_/2)*CF_; i += nthr) {
        int col = i >> 10, k = i & 1023;
        store_Bsplit(g_Bw1c, col, k, e2ts_w1[(size_t)col * CF_ + k]);
    }
    // trec = relu(z @ z2t_w^T + b)
    for (int tile = bid; tile < 32; tile += nb) {
        int bm = (tile >> 2) * 128, bn = (tile & 3) * 128;
        float acc[4][8];
        #pragma unroll
        for (int i = 0; i < 4; i++)
            #pragma unroll
            for (int j = 0; j < 8; j++) acc[i][j] = 0.f;
        gemm128(z, Z_, z2t_w, Z_, Z_, bm, bn, sA, sB, acc);
        const int tx = tid & 15, ty = tid >> 4;
        #pragma unroll
        for (int i = 0; i < 4; i++) {
            int gm = bm + ty*4 + i;
            #pragma unroll
            for (int j = 0; j < 8; j++) {
                int gn = bn + tx*8 + j;
                g_trec[(size_t)gm * TD_ + gn] = fmaxf(acc[i][j] + z2t_b[gn], 0.f);
            }
        }
    }
    grid_sync();

    // ================= setup phase S1: P_* (interleaved store) =================
    for (int tile = bid; tile < 768; tile += nb) {
        int which = tile >> 8;
        int rem   = tile & 255;
        int bm = (rem >> 5) * 128, bn = (rem & 31) * 128;
        const float* Wih  = (which == 0) ? Wih_a : (which == 1) ? Wih_r : Wih_t;
        const float* bias = (which == 0) ? b_a   : (which == 1) ? b_r   : b_t;
        float* P          = (which == 0) ? g_Pa  : (which == 1) ? g_Pr  : g_Pt;
        int ldb = (which == 0) ? (TD_+A_) : (which == 1) ? (TD_+A_+R_) : (TD_+A_+1);
        float acc[4][8];
        #pragma unroll
        for (int i = 0; i < 4; i++)
            #pragma unroll
            for (int j = 0; j < 8; j++) acc[i][j] = 0.f;
        gemm128(g_trec, TD_, Wih, ldb, TD_, bm, bn, sA, sB, acc);
        const int tx = tid & 15, ty = tid >> 4;
        #pragma unroll
        for (int i = 0; i < 4; i++) {
            int gm = bm + ty*4 + i;
            #pragma unroll
            for (int j = 0; j < 8; j++) {
                int gn = bn + tx*8 + j;     // gate-major index
                int g = gn >> 10, jj = gn & 1023;
                P[(size_t)gm * G_ + jj*4 + g] = acc[i][j] + bias[gn];
            }
        }
    }
    grid_sync();

    // ================= time loop: 2 phases per step =================
    for (int t = 0; t < T_; t++) {
        const int p = t & 1, q = p ^ 1;

        // ---- Phase A: a-GEMM+a-cell (256) + ts-hidden(t-1) (32) + res-head(t-1) (64)
        int nA = (t > 0) ? 352 : 256;
        for (int item = bid; item < nA; item += nb) {
            if (item < 256) {
                int tm = item & 7, tn = item >> 3;       // tn-major for L2 reuse
                mma_direct(g_AhA[p], g_AlA[p], g_BcA, tm, tn, 2,
                           nullptr, nullptr,
                           g_Pa, g_WaA, nullptr, nullptr, nullptr, nullptr,
                           g_actidx, g_cA, g_hA,
                           g_AhA[q], g_AlA[q], 0u);
            } else if (item < 288) {
                int tl = item - 256;
                int tm = tl >> 2, tn = tl & 3;
                mma_direct(g_AhT[p], g_AlT[p], g_Bw1c, tm, tn, 1,
                           g_hidden, e2ts_b1,
                           nullptr, nullptr, nullptr, nullptr, nullptr, nullptr,
                           nullptr, nullptr, nullptr, nullptr, nullptr, 0u);
            } else {
                res_head_block(item - 288, t - 1, e2res_w, e2res_b, out, sA, sB);
            }
        }
        grid_sync();

        // ---- Phase B: lights FIRST (act-head 128 + ts-dot 16), then
        //      r-GEMM+r-cell (256) + t-GEMM+t-cell (256) with spin handshake ----
        const int L = (t > 0) ? 144 : 128;
        const unsigned tgt = 128u + 144u * (unsigned)t;
        for (int item = bid; item < L + 512; item += nb) {
            if (item < 128) {
                // act head + argmax (8 rows x 64 cols)
                int blk = item;
                int m0 = blk * 8;
                float a0 = 0.f;
                const float* h = g_hA;
                const int rr = tid >> 6, cc = tid & 63;
                for (int kb = 0; kb < CF_; kb += 32) {
                    if (tid < 64) {
                        int r = tid >> 3, c4 = (tid & 7) * 4;
                        float4 v = *(const float4*)&h[(size_t)(m0 + r) * CF_ + kb + c4];
                        sA[r*32 + c4+0] = v.x; sA[r*32 + c4+1] = v.y;
                        sA[r*32 + c4+2] = v.z; sA[r*32 + c4+3] = v.w;
                    }
                    {
                        int ccw = tid >> 3, k4 = (tid & 7) * 4;   // 512 float4s
                        float4 v = *(const float4*)&e2act_w[(size_t)ccw * CF_ + kb + k4];
                        sB[(k4+0)*64 + ccw] = v.x; sB[(k4+1)*64 + ccw] = v.y;
                        sB[(k4+2)*64 + ccw] = v.z; sB[(k4+3)*64 + ccw] = v.w;
                    }
                    __syncthreads();
                    #pragma unroll
                    for (int k = 0; k < 32; k++)
                        a0 += sA[rr*32 + k] * sB[k*64 + cc];
                    __syncthreads();
                }
                {
                    float v0 = a0 + e2act_b[cc];
                    sA[rr*64 + cc] = v0;
                    out[(size_t)(m0 + rr) * (T_*A_) + t*A_ + cc] = v0;
                }
                __syncthreads();
                if (tid < 8) {
                    float bv = -INFINITY; int bi = 0;
                    for (int n = 0; n < A_; n++) {
                        float v = sA[tid*64 + n];
                        if (v > bv) { bv = v; bi = n; }
                    }
                    g_actidx[m0 + tid] = bi;
                }
                __syncthreads();
                if (tid == 0) { __threadfence(); atomicAdd(&g_done, 1u); }
            } else if (item < L) {
                // ts-dot for step t-1: 16 chunks x 64 rows, warp per row
                int c = item - 128;
                for (int rl = wid; rl < 64; rl += 16) {
                    int m = c * 64 + rl;
                    const float* hrow = &g_hidden[(size_t)m * (CF_/2)];
                    float s = 0.f;
                    for (int j = lane; j < CF_/2; j += 32) s += hrow[j] * e2ts_w2[j];
                    #pragma unroll
                    for (int off = 16; off; off >>= 1)
                        s += __shfl_down_sync(0xffffffffu, s, off);
                    if (lane == 0) {
                        float v = s + e2ts_b2[0];
                        g_tsv[m] = v;
                        out[TS_BASE + (size_t)m * T_ + (t - 1)] = v;
                    }
                }
                __syncthreads();
                if (tid == 0) { __threadfence(); atomicAdd(&g_done, 1u); }
            } else {
                int idx = item - L;
                int s = idx >> 8, rem = idx & 255;
                int tm = rem & 7, tn = rem >> 3;
                if (s == 0) {
                    mma_direct(g_AhR[p], g_AlR[p], g_BcR, tm, tn, 3,
                               nullptr, nullptr,
                               g_Pr, g_WaR, g_WrR, g_residx, nullptr, nullptr,
                               g_actidx, g_cR, g_hR,
                               g_AhR[q], g_AlR[q], tgt);
                } else {
                    mma_direct(g_AhT[p], g_AlT[p], g_BcT, tm, tn, 4,
                               nullptr, nullptr,
                               g_Pt, g_WaT, nullptr, nullptr, g_WtT, g_tsv,
                               g_actidx, g_cT, nullptr,
                               g_AhT[q], g_AlT[q], tgt);
                }
            }
        }
        grid_sync();
    }

    // ================= epilogue =================
    // E1: ts-hidden(63) (32 tiles, reads AhT[0]) + res-head(63) (64 blocks)
    for (int item = bid; item < 96; item += nb) {
        if (item < 32) {
            int tm = item >> 2, tn = item & 3;
            mma_direct(g_AhT[0], g_AlT[0], g_Bw1c, tm, tn, 1,
                       g_hidden, e2ts_b1,
                       nullptr, nullptr, nullptr, nullptr, nullptr, nullptr,
                       nullptr, nullptr, nullptr, nullptr, nullptr, 0u);
        } else {
            res_head_block(item - 32, T_ - 1, e2res_w, e2res_b, out, sA, sB);
        }
    }
    grid_sync();

    // E2: ts-dot(63) + final softmaxes
    for (int m = bid * 16 + wid; m < B_; m += nb * 16) {
        const float* hrow = &g_hidden[(size_t)m * (CF_/2)];
        float s = 0.f;
        for (int j = lane; j < CF_/2; j += 32) s += hrow[j] * e2ts_w2[j];
        #pragma unroll
        for (int off = 16; off; off >>= 1)
            s += __shfl_down_sync(0xffffffffu, s, off);
        if (lane == 0)
            out[TS_BASE + (size_t)m * T_ + (T_ - 1)] = s + e2ts_b2[0];
    }
    for (int r = bid * 16 + wid; r < B_*T_; r += nb * 16) {    // acts, W=64
        float* row = out + (size_t)r * A_;
        float v0 = row[lane], v1 = row[lane + 32];
        float mx = fmaxf(v0, v1);
        #pragma unroll
        for (int off = 16; off; off >>= 1)
            mx = fmaxf(mx, __shfl_xor_sync(0xffffffffu, mx, off));
        float e0 = expf(v0 - mx), e1 = expf(v1 - mx);
        float s = e0 + e1;
        #pragma unroll
        for (int off = 16; off; off >>= 1)
            s += __shfl_xor_sync(0xffffffffu, s, off);
        float inv = 1.f / s;
        row[lane] = e0 * inv; row[lane + 32] = e1 * inv;
    }
    for (int r = bid * 16 + wid; r < B_*T_; r += nb * 16) {    // ress, W=128
        float* row = out + RESS_BASE + (size_t)r * R_;
        float v[4];
        float mx = -INFINITY;
        #pragma unroll
        for (int u = 0; u < 4; u++) { v[u] = row[lane + u*32]; mx = fmaxf(mx, v[u]); }
        #pragma unroll
        for (int off = 16; off; off >>= 1)
            mx = fmaxf(mx, __shfl_xor_sync(0xffffffffu, mx, off));
        float e[4]; float s = 0.f;
        #pragma unroll
        for (int u = 0; u < 4; u++) { e[u] = expf(v[u] - mx); s += e[u]; }
        #pragma unroll
        for (int off = 16; off; off >>= 1)
            s += __shfl_xor_sync(0xffffffffu, s, off);
        float inv = 1.f / s;
        #pragma unroll
        for (int u = 0; u < 4; u++) row[lane + u*32] = e[u] * inv;
    }
}

// ---------------- host -------------------------------------------------------
extern "C" void kernel_launch(void* const* d_in, const int* in_sizes, int n_in,
                              void* d_out, int out_size)
{
    const float* z        = (const float*)d_in[0];
    const float* z2t_w    = (const float*)d_in[1];
    const float* z2t_b    = (const float*)d_in[2];
    const float* Wih_a    = (const float*)d_in[3];
    const float* Whh_a    = (const float*)d_in[4];
    const float* b_a      = (const float*)d_in[5];
    const float* Wih_r    = (const float*)d_in[6];
    const float* Whh_r    = (const float*)d_in[7];
    const float* b_r      = (const float*)d_in[8];
    const float* Wih_t    = (const float*)d_in[9];
    const float* Whh_t    = (const float*)d_in[10];
    const float* b_t      = (const float*)d_in[11];
    const float* e2act_w  = (const float*)d_in[12];
    const float* e2act_b  = (const float*)d_in[13];
    const float* e2res_w  = (const float*)d_in[14];
    const float* e2res_b  = (const float*)d_in[15];
    const float* e2ts_w1  = (const float*)d_in[16];
    const float* e2ts_b1  = (const float*)d_in[17];
    const float* e2ts_w2  = (const float*)d_in[18];
    const float* e2ts_b2  = (const float*)d_in[19];
    float* out = (float*)d_out;

    int dev = 0;
    cudaGetDevice(&dev);
    int nsm = 0;
    cudaDeviceGetAttribute(&nsm, cudaDevAttrMultiProcessorCount, dev);
    int occ = 0;
    cudaOccupancyMaxActiveBlocksPerMultiprocessor(&occ, decoder_all, NT, 0);
    if (occ < 1) occ = 1;
    if (nsm < 1) nsm = 1;
    int nb = nsm * occ;

    decoder_all<<<nb, NT>>>(
        z, z2t_w, z2t_b,
        Wih_a, Whh_a, b_a,
        Wih_r, Whh_r, b_r,
        Wih_t, Whh_t, b_t,
        e2act_w, e2act_b, e2res_w, e2res_b,
        e2ts_w1, e2ts_b1, e2ts_w2, e2ts_b2,
        out);
}

// round 14
// speedup vs baseline: 1.1281x; 1.1281x over previous
#include <cuda_runtime.h>
#include <math.h>
#include <stdint.h>

// Problem dims
#define B_   1024
#define Z_   256
#define TD_  512
#define CF_  1024
#define A_   64
#define R_   128
#define T_   64
#define G_   4096   // 4*CF

// Output layout: acts [B,T,A] | ts [B,T] | ress [B,T,R]
#define TS_BASE   (B_*T_*A_)
#define RESS_BASE (TS_BASE + B_*T_)

#define NT 512     // threads per CTA

// ---------------- scratch (device globals) -----------------------------------
__device__ float g_trec[B_*TD_];
__device__ float g_Pa[B_*G_];      // interleaved: P[m][j*4+g]
__device__ float g_Pr[B_*G_];
__device__ float g_Pt[B_*G_];
__device__ float g_GR[B_*G_];      // raw gate GEMM results (r,t LSTMs)
__device__ float g_GT[B_*G_];
__device__ float g_hA[B_*CF_];     // plain h (act head)
__device__ float g_hR[B_*CF_];     // plain h (res head)
__device__ float g_cA[B_*CF_];
__device__ float g_cR[B_*CF_];
__device__ float g_cT[B_*CF_];
__device__ float g_hidden[B_*(CF_/2)];
// pre-split tf32 hi/lo A operands in m16n8k8 fragment layout
__device__ float g_AhA[2][B_*CF_], g_AlA[2][B_*CF_];   // ping-pong (fused writer)
__device__ float g_AhR[B_*CF_], g_AlR[B_*CF_];
__device__ float g_AhT[B_*CF_], g_AlT[B_*CF_];
// B operands: hi/lo INTERLEAVED per lane (uint4 = {hi0,hi1,lo0,lo1}) -> 1 LDG.128
__device__ float g_BcA[2*G_*CF_];   // Whh_a (gate-interleaved cols)
__device__ float g_BcR[2*G_*CF_];
__device__ float g_BcT[2*G_*CF_];
__device__ float g_Bw1c[CF_*CF_];   // e2ts_w1 (CF/2 cols x CF k x 2)
// one-hot column tables (interleaved per row: [idx][j*4+g])
__device__ float g_WaA[A_*G_];
__device__ float g_WaR[A_*G_];
__device__ float g_WrR[R_*G_];
__device__ float g_WaT[A_*G_];
__device__ float g_WtT[G_];
__device__ int   g_actidx[B_];
__device__ int   g_residx[B_];
__device__ float g_tsv[B_];

__device__ unsigned g_bar_count = 0;
__device__ unsigned g_bar_gen   = 0;

// ---------------- software grid barrier --------------------------------------
__device__ __forceinline__ void grid_sync() {
    __syncthreads();
    if (threadIdx.x == 0) {
        __threadfence();
        unsigned gen = *(volatile unsigned*)&g_bar_gen;
        if (atomicAdd(&g_bar_count, 1u) == gridDim.x - 1) {
            g_bar_count = 0;
            __threadfence();
            atomicAdd(&g_bar_gen, 1u);
        } else {
            while (*(volatile unsigned*)&g_bar_gen == gen) __nanosleep(64);
        }
        __threadfence();
    }
    __syncthreads();
}

// ---------------- tf32 helpers ------------------------------------------------
__device__ __forceinline__ uint32_t f2tf(float x) {
    uint32_t u;
    asm("cvt.rna.tf32.f32 %0, %1;" : "=r"(u) : "f"(x));
    return u;
}

__device__ __forceinline__ void mma8(float* c, const uint32_t* a, const uint32_t* b) {
    asm volatile(
        "mma.sync.aligned.m16n8k8.row.col.f32.tf32.tf32.f32 "
        "{%0,%1,%2,%3}, {%4,%5,%6,%7}, {%8,%9}, {%0,%1,%2,%3};"
        : "+f"(c[0]), "+f"(c[1]), "+f"(c[2]), "+f"(c[3])
        : "r"(a[0]), "r"(a[1]), "r"(a[2]), "r"(a[3]), "r"(b[0]), "r"(b[1]));
}

// A-frag split-store: element (m, k) of an A operand [1024 x 1024]
__device__ __forceinline__ void store_Asplit(float* Ah, float* Al, int m, int k, float v) {
    int r = m & 15;
    int lane = (r & 7) * 4 + (k & 3);
    int reg  = (r >> 3) + 2 * ((k >> 2) & 1);
    size_t off = (((size_t)((m >> 4) * 128 + (k >> 3)) * 32 + lane) * 4 + reg);
    float hi = __uint_as_float(f2tf(v));
    Ah[off] = hi;
    Al[off] = __uint_as_float(f2tf(v - hi));
}

// B-frag combined split-store: output col cg, k (0..1023).
__device__ __forceinline__ void store_Bsplit(float* Bc, int cg, int k, float v) {
    int lanei = (cg & 7) * 4 + (k & 3);
    int reg   = (k >> 2) & 1;
    size_t off = ((size_t)((cg >> 3) * 128 + (k >> 3)) * 128) + lanei * 4 + reg;
    float hi = __uint_as_float(f2tf(v));
    Bc[off]     = hi;
    Bc[off + 2] = __uint_as_float(f2tf(v - hi));
}

__device__ __forceinline__ float sigm(float x) { return 1.f / (1.f + expf(-x)); }

// ---------------- direct-LDG 3xTF32 mma tile (512 threads) -------------------
// C[128x128] += A@B^T, K=1024. Warp grid 4x4, each warp 32x32 output.
// mode 0: raw store stride 4096 (gates).
// mode 1: bias+relu store stride 512 (ts hidden).
// mode 2: fused a-cell epilogue (P + one-hot col + LSTM cell, writes h/c/splits).
__device__ void mma_direct(const float* __restrict__ Ah, const float* __restrict__ Al,
                           const float* __restrict__ Bc,
                           int tm, int tn, int mode,
                           float* __restrict__ Gout, const float* __restrict__ bias,
                           const float* __restrict__ Ppre, const float* __restrict__ Wtab,
                           const int* __restrict__ actidx, float* __restrict__ cbuf,
                           float* __restrict__ hplain,
                           float* __restrict__ Ahout, float* __restrict__ Alout)
{
    const int tid  = threadIdx.x;
    const int lane = tid & 31;
    const int warp = tid >> 5;            // 0..15
    const int wm = warp >> 2, wn = warp & 3;

    const uint4* A4h = (const uint4*)Ah;
    const uint4* A4l = (const uint4*)Al;
    const uint4* B4  = (const uint4*)Bc;

    int aidx[2], bidx[4];
    #pragma unroll
    for (int m = 0; m < 2; m++)
        aidx[m] = (tm * 8 + wm * 2 + m) * 4096 + lane;   // uint4 units, +k8*32
    #pragma unroll
    for (int n = 0; n < 4; n++)
        bidx[n] = (tn * 16 + wn * 4 + n) * 4096 + lane;  // uint4 units, +k8*32

    float acc[2][4][4];
    #pragma unroll
    for (int m = 0; m < 2; m++)
        #pragma unroll
        for (int n = 0; n < 4; n++)
            #pragma unroll
            for (int q = 0; q < 4; q++) acc[m][n][q] = 0.f;

    uint4 ah0[2], al0[2], ah1[2], al1[2];
    uint4 bc0[4], bc1[4];

    #pragma unroll
    for (int m = 0; m < 2; m++) { ah0[m] = A4h[aidx[m]]; al0[m] = A4l[aidx[m]]; }
    #pragma unroll
    for (int n = 0; n < 4; n++) bc0[n] = B4[bidx[n]];

    for (int k8 = 0; k8 < 128; k8 += 2) {
        // prefetch regs k8+1
        #pragma unroll
        for (int m = 0; m < 2; m++) {
            int o = aidx[m] + (k8 + 1) * 32;
            ah1[m] = A4h[o]; al1[m] = A4l[o];
        }
        #pragma unroll
        for (int n = 0; n < 4; n++)
            bc1[n] = B4[bidx[n] + (k8 + 1) * 32];
        #pragma unroll
        for (int m = 0; m < 2; m++)
            #pragma unroll
            for (int n = 0; n < 4; n++) {
                mma8(acc[m][n], (const uint32_t*)&ah0[m], (const uint32_t*)&bc0[n].x);
                mma8(acc[m][n], (const uint32_t*)&ah0[m], (const uint32_t*)&bc0[n].z);
                mma8(acc[m][n], (const uint32_t*)&al0[m], (const uint32_t*)&bc0[n].x);
            }
        // prefetch regs k8+2
        if (k8 + 2 < 128) {
            #pragma unroll
            for (int m = 0; m < 2; m++) {
                int o = aidx[m] + (k8 + 2) * 32;
                ah0[m] = A4h[o]; al0[m] = A4l[o];
            }
            #pragma unroll
            for (int n = 0; n < 4; n++)
                bc0[n] = B4[bidx[n] + (k8 + 2) * 32];
        }
        #pragma unroll
        for (int m = 0; m < 2; m++)
            #pragma unroll
            for (int n = 0; n < 4; n++) {
                mma8(acc[m][n], (const uint32_t*)&ah1[m], (const uint32_t*)&bc1[n].x);
                mma8(acc[m][n], (const uint32_t*)&ah1[m], (const uint32_t*)&bc1[n].z);
                mma8(acc[m][n], (const uint32_t*)&al1[m], (const uint32_t*)&bc1[n].x);
            }
    }

    // ---- epilogue ----
    if (mode == 0) {
        #pragma unroll
        for (int m = 0; m < 2; m++) {
            int r1 = tm * 128 + wm * 32 + m * 16 + (lane >> 2);
            #pragma unroll
            for (int n = 0; n < 4; n++) {
                int cg = tn * 128 + wn * 32 + n * 8 + (lane & 3) * 2;
                *(float2*)&Gout[(size_t)r1 * G_ + cg] =
                    make_float2(acc[m][n][0], acc[m][n][1]);
                *(float2*)&Gout[(size_t)(r1 + 8) * G_ + cg] =
                    make_float2(acc[m][n][2], acc[m][n][3]);
            }
        }
    } else if (mode == 1) {
        #pragma unroll
        for (int m = 0; m < 2; m++) {
            int r1 = tm * 128 + wm * 32 + m * 16 + (lane >> 2);
            #pragma unroll
            for (int n = 0; n < 4; n++) {
                int cg = tn * 128 + wn * 32 + n * 8 + (lane & 3) * 2;
                float v0 = fmaxf(acc[m][n][0] + bias[cg],     0.f);
                float v1 = fmaxf(acc[m][n][1] + bias[cg + 1], 0.f);
                float v2 = fmaxf(acc[m][n][2] + bias[cg],     0.f);
                float v3 = fmaxf(acc[m][n][3] + bias[cg + 1], 0.f);
                *(float2*)&Gout[(size_t)r1 * (CF_/2) + cg]       = make_float2(v0, v1);
                *(float2*)&Gout[(size_t)(r1 + 8) * (CF_/2) + cg] = make_float2(v2, v3);
            }
        }
    } else {
        // mode 2: fused a-cell. Thread holds gate pair (g0,g1) or (g2,g3) of
        // column j for rows r1 and r1+8; partner lane^1 holds the other pair.
        const bool low = ((lane & 1) == 0);
        #pragma unroll
        for (int m = 0; m < 2; m++) {
            int r1 = tm * 128 + wm * 32 + m * 16 + (lane >> 2);
            #pragma unroll
            for (int n = 0; n < 4; n++) {
                int cg = tn * 128 + wn * 32 + n * 8 + (lane & 3) * 2;
                int j  = cg >> 2;
                float o0 = acc[m][n][0], o1 = acc[m][n][1];
                float o2 = acc[m][n][2], o3 = acc[m][n][3];
                float p0 = __shfl_xor_sync(0xffffffffu, o0, 1);
                float p1 = __shfl_xor_sync(0xffffffffu, o1, 1);
                float p2 = __shfl_xor_sync(0xffffffffu, o2, 1);
                float p3 = __shfl_xor_sync(0xffffffffu, o3, 1);
                if (low) {
                    {
                        int a1 = actidx[r1];
                        float2 pA = *(const float2*)&Ppre[(size_t)r1 * G_ + j*4];
                        float2 pB = *(const float2*)&Ppre[(size_t)r1 * G_ + j*4 + 2];
                        float2 wA = *(const float2*)&Wtab[(size_t)a1 * G_ + j*4];
                        float2 wB = *(const float2*)&Wtab[(size_t)a1 * G_ + j*4 + 2];
                        float gi = o0 + pA.x + wA.x;
                        float gf = o1 + pA.y + wA.y;
                        float gg = p0 + pB.x + wB.x;
                        float go = p1 + pB.y + wB.y;
                        size_t off = (size_t)r1 * CF_ + j;
                        float cn = sigm(gf) * cbuf[off] + sigm(gi) * tanhf(gg);
                        cbuf[off] = cn;
                        float hv = sigm(go) * tanhf(cn);
                        hplain[off] = hv;
                        store_Asplit(Ahout, Alout, r1, j, hv);
                    }
                    {
                        int r2 = r1 + 8;
                        int a2 = actidx[r2];
                        float2 pA = *(const float2*)&Ppre[(size_t)r2 * G_ + j*4];
                        float2 pB = *(const float2*)&Ppre[(size_t)r2 * G_ + j*4 + 2];
                        float2 wA = *(const float2*)&Wtab[(size_t)a2 * G_ + j*4];
                        float2 wB = *(const float2*)&Wtab[(size_t)a2 * G_ + j*4 + 2];
                        float gi = o2 + pA.x + wA.x;
                        float gf = o3 + pA.y + wA.y;
                        float gg = p2 + pB.x + wB.x;
                        float go = p3 + pB.y + wB.y;
                        size_t off = (size_t)r2 * CF_ + j;
                        float cn = sigm(gf) * cbuf[off] + sigm(gi) * tanhf(gg);
                        cbuf[off] = cn;
                        float hv = sigm(go) * tanhf(cn);
                        hplain[off] = hv;
                        store_Asplit(Ahout, Alout, r2, j, hv);
                    }
                }
            }
        }
    }
}

// ---------------- fp32 SIMT 128x128 tile, 512 threads (setup GEMMs only) -----
__device__ __forceinline__ void gemm128(
    const float* __restrict__ A, int lda,
    const float* __restrict__ B, int ldb,
    int K, int bm, int bn,
    float* sA, float* sB, float acc[4][8])
{
    const int tid  = threadIdx.x;
    const int tx   = tid & 15, ty = tid >> 4;   // ty 0..31
    const int lrow = tid >> 2;                  // 0..127
    const int lseg = tid & 3;
    const bool bvec = ((ldb & 3) == 0);

    for (int kb = 0; kb < K; kb += 16) {
        {
            float4 v = *(const float4*)&A[(size_t)(bm + lrow) * lda + kb + lseg * 4];
            sA[(lseg*4+0)*128 + lrow] = v.x; sA[(lseg*4+1)*128 + lrow] = v.y;
            sA[(lseg*4+2)*128 + lrow] = v.z; sA[(lseg*4+3)*128 + lrow] = v.w;
        }
        {
            const float* bp = &B[(size_t)(bn + lrow) * ldb + kb + lseg * 4];
            float4 v;
            if (bvec) v = *(const float4*)bp;
            else { v.x = bp[0]; v.y = bp[1]; v.z = bp[2]; v.w = bp[3]; }
            sB[(lseg*4+0)*128 + lrow] = v.x; sB[(lseg*4+1)*128 + lrow] = v.y;
            sB[(lseg*4+2)*128 + lrow] = v.z; sB[(lseg*4+3)*128 + lrow] = v.w;
        }
        __syncthreads();
        #pragma unroll
        for (int k = 0; k < 16; k++) {
            float a[4], b[8];
            *(float4*)&a[0] = *(const float4*)&sA[k*128 + ty*4];
            *(float4*)&b[0] = *(const float4*)&sB[k*128 + tx*8];
            *(float4*)&b[4] = *(const float4*)&sB[k*128 + tx*8 + 4];
            #pragma unroll
            for (int i = 0; i < 4; i++)
                #pragma unroll
                for (int j = 0; j < 8; j++)
                    acc[i][j] += a[i] * b[j];
        }
        __syncthreads();
    }
}

// ---------------- the whole decoder as ONE persistent kernel -----------------
__global__ __launch_bounds__(NT, 1) void decoder_all(
    const float* __restrict__ z,
    const float* __restrict__ z2t_w, const float* __restrict__ z2t_b,
    const float* __restrict__ Wih_a, const float* __restrict__ Whh_a, const float* __restrict__ b_a,
    const float* __restrict__ Wih_r, const float* __restrict__ Whh_r, const float* __restrict__ b_r,
    const float* __restrict__ Wih_t, const float* __restrict__ Whh_t, const float* __restrict__ b_t,
    const float* __restrict__ e2act_w, const float* __restrict__ e2act_b,
    const float* __restrict__ e2res_w, const float* __restrict__ e2res_b,
    const float* __restrict__ e2ts_w1, const float* __restrict__ e2ts_b1,
    const float* __restrict__ e2ts_w2, const float* __restrict__ e2ts_b2,
    float* __restrict__ out)
{
    __shared__ float sA[2048];
    __shared__ float sB[4096];
    const int tid = threadIdx.x;
    const int bid = blockIdx.x;
    const int nb  = gridDim.x;
    const int nthr = nb * NT;
    const int gthr = bid * NT + tid;
    const int lane = tid & 31;
    const int wid  = tid >> 5;           // 0..15

    // ================= setup phase S0 =================
    for (int i = gthr; i < B_*CF_; i += nthr) {
        g_hA[i] = 0.f; g_cA[i] = 0.f;
        g_hR[i] = 0.f; g_cR[i] = 0.f;
        g_cT[i] = 0.f;
        g_AhA[0][i] = 0.f; g_AlA[0][i] = 0.f;
        g_AhA[1][i] = 0.f; g_AlA[1][i] = 0.f;
        g_AhR[i] = 0.f; g_AlR[i] = 0.f;
        g_AhT[i] = 0.f; g_AlT[i] = 0.f;
    }
    for (int i = gthr; i < B_; i += nthr) {
        g_actidx[i] = A_ - 1; g_residx[i] = R_ - 1; g_tsv[i] = 0.f;
    }
    // one-hot column tables (interleaved per row: [idx][j*4+g])
    for (int i = gthr; i < A_*G_; i += nthr) {
        int a = i >> 12, qy = i & 4095, j = qy >> 2, g = qy & 3;
        g_WaA[i] = Wih_a[(size_t)(g*CF_ + j) * (TD_+A_)      + TD_ + a];
        g_WaR[i] = Wih_r[(size_t)(g*CF_ + j) * (TD_+A_+R_)   + TD_ + a];
        g_WaT[i] = Wih_t[(size_t)(g*CF_ + j) * (TD_+A_+1)    + TD_ + a];
    }
    for (int i = gthr; i < R_*G_; i += nthr) {
        int r = i >> 12, qy = i & 4095, j = qy >> 2, g = qy & 3;
        g_WrR[i] = Wih_r[(size_t)(g*CF_ + j) * (TD_+A_+R_) + TD_ + A_ + r];
    }
    for (int i = gthr; i < G_; i += nthr) {
        int j = i >> 2, g = i & 3;
        g_WtT[i] = Wih_t[(size_t)(g*CF_ + j) * (TD_+A_+1) + TD_ + A_];
    }
    // Whh pre-split into combined fragment layout (gate-interleaved col order)
    for (int i = gthr; i < 3*G_*CF_; i += nthr) {
        int s  = i >> 22;
        int r  = i & (G_*CF_ - 1);
        int cg = r >> 10, k = r & 1023;
        int j = cg >> 2, g = cg & 3;
        const float* W = (s == 0) ? Whh_a : (s == 1) ? Whh_r : Whh_t;
        float* Bc = (s == 0) ? g_BcA : (s == 1) ? g_BcR : g_BcT;
        store_Bsplit(Bc, cg, k, W[(size_t)(g*CF_ + j) * CF_ + k]);
    }
    // e2ts_w1 pre-split (identity col order)
    for (int i = gthr; i < (CF_/2)*CF_; i += nthr) {
        int col = i >> 10, k = i & 1023;
        store_Bsplit(g_Bw1c, col, k, e2ts_w1[(size_t)col * CF_ + k]);
    }
    // trec = relu(z @ z2t_w^T + b)
    for (int tile = bid; tile < 32; tile += nb) {
        int bm = (tile >> 2) * 128, bn = (tile & 3) * 128;
        float acc[4][8];
        #pragma unroll
        for (int i = 0; i < 4; i++)
            #pragma unroll
            for (int j = 0; j < 8; j++) acc[i][j] = 0.f;
        gemm128(z, Z_, z2t_w, Z_, Z_, bm, bn, sA, sB, acc);
        const int tx = tid & 15, ty = tid >> 4;
        #pragma unroll
        for (int i = 0; i < 4; i++) {
            int gm = bm + ty*4 + i;
            #pragma unroll
            for (int j = 0; j < 8; j++) {
                int gn = bn + tx*8 + j;
                g_trec[(size_t)gm * TD_ + gn] = fmaxf(acc[i][j] + z2t_b[gn], 0.f);
            }
        }
    }
    grid_sync();

    // ================= setup phase S1: P_* (interleaved store) =================
    for (int tile = bid; tile < 768; tile += nb) {
        int which = tile >> 8;
        int rem   = tile & 255;
        int bm = (rem >> 5) * 128, bn = (rem & 31) * 128;
        const float* Wih  = (which == 0) ? Wih_a : (which == 1) ? Wih_r : Wih_t;
        const float* bias = (which == 0) ? b_a   : (which == 1) ? b_r   : b_t;
        float* P          = (which == 0) ? g_Pa  : (which == 1) ? g_Pr  : g_Pt;
        int ldb = (which == 0) ? (TD_+A_) : (which == 1) ? (TD_+A_+R_) : (TD_+A_+1);
        float acc[4][8];
        #pragma unroll
        for (int i = 0; i < 4; i++)
            #pragma unroll
            for (int j = 0; j < 8; j++) acc[i][j] = 0.f;
        gemm128(g_trec, TD_, Wih, ldb, TD_, bm, bn, sA, sB, acc);
        const int tx = tid & 15, ty = tid >> 4;
        #pragma unroll
        for (int i = 0; i < 4; i++) {
            int gm = bm + ty*4 + i;
            #pragma unroll
            for (int j = 0; j < 8; j++) {
                int gn = bn + tx*8 + j;     // gate-major index
                int g = gn >> 10, jj = gn & 1023;
                P[(size_t)gm * G_ + jj*4 + g] = acc[i][j] + bias[gn];
            }
        }
    }
    grid_sync();

    // ================= time loop =================
    for (int t = 0; t < T_; t++) {
        const int p = t & 1, q = p ^ 1;

        // ---- P1: a-tiles (t==0: all 256; else first 200, rest done in P5(t-1))
        //          + r/t GEMMs (512) + ts-dot(t-1) (16) ----
        int na = (t == 0) ? 256 : 200;
        int nheavy = na + 512;
        int nit = (t > 0) ? nheavy + 16 : nheavy;
        for (int item = bid; item < nit; item += nb) {
            if (item < na) {
                int tm = item & 7, tn = item >> 3;     // a-tiles 0..na-1
                mma_direct(g_AhA[p], g_AlA[p], g_BcA, tm, tn, 2,
                           nullptr, nullptr,
                           g_Pa, g_WaA, g_actidx, g_cA, g_hA,
                           g_AhA[q], g_AlA[q]);
            } else if (item < nheavy) {
                int idx = item - na;
                int s = idx >> 8, rem = idx & 255;
                int tm = rem & 7, tn = rem >> 3;
                const float* Ah = (s == 0) ? g_AhR : g_AhT;
                const float* Al = (s == 0) ? g_AlR : g_AlT;
                const float* Bc = (s == 0) ? g_BcR : g_BcT;
                float* Gp       = (s == 0) ? g_GR  : g_GT;
                mma_direct(Ah, Al, Bc, tm, tn, 0, Gp, nullptr,
                           nullptr, nullptr, nullptr, nullptr, nullptr,
                           nullptr, nullptr);
            } else {
                // ts-dot for step t-1: 16 chunks x 64 rows, warp per row
                int c = item - nheavy;
                for (int rl = wid; rl < 64; rl += 16) {
                    int m = c * 64 + rl;
                    const float* hrow = &g_hidden[(size_t)m * (CF_/2)];
                    float s = 0.f;
                    for (int j = lane; j < CF_/2; j += 32) s += hrow[j] * e2ts_w2[j];
                    #pragma unroll
                    for (int off = 16; off; off >>= 1)
                        s += __shfl_down_sync(0xffffffffu, s, off);
                    if (lane == 0) {
                        float v = s + e2ts_b2[0];
                        g_tsv[m] = v;
                        out[TS_BASE + (size_t)m * T_ + (t - 1)] = v;
                    }
                }
            }
        }
        grid_sync();

        // ---- P3: act head + argmax (128 blocks x 8 rows, exact fp32) ----
        for (int blk = bid; blk < 128; blk += nb) {
            int m0 = blk * 8;
            float a0 = 0.f;
            const float* h = g_hA;
            const int rr = tid >> 6, cc = tid & 63;
            for (int kb = 0; kb < CF_; kb += 32) {
                if (tid < 64) {
                    int r = tid >> 3, c4 = (tid & 7) * 4;
                    float4 v = *(const float4*)&h[(size_t)(m0 + r) * CF_ + kb + c4];
                    sA[r*32 + c4+0] = v.x; sA[r*32 + c4+1] = v.y;
                    sA[r*32 + c4+2] = v.z; sA[r*32 + c4+3] = v.w;
                }
                {
                    int ccw = tid >> 3, k4 = (tid & 7) * 4;   // 512 float4s
                    float4 v = *(const float4*)&e2act_w[(size_t)ccw * CF_ + kb + k4];
                    sB[(k4+0)*64 + ccw] = v.x; sB[(k4+1)*64 + ccw] = v.y;
                    sB[(k4+2)*64 + ccw] = v.z; sB[(k4+3)*64 + ccw] = v.w;
                }
                __syncthreads();
                #pragma unroll
                for (int k = 0; k < 32; k++)
                    a0 += sA[rr*32 + k] * sB[k*64 + cc];
                __syncthreads();
            }
            {
                float v0 = a0 + e2act_b[cc];
                sA[rr*64 + cc] = v0;
                out[(size_t)(m0 + rr) * (T_*A_) + t*A_ + cc] = v0;
            }
            __syncthreads();
            if (tid < 8) {
                float bv = -INFINITY; int bi = 0;
                for (int n = 0; n < A_; n++) {
                    float v = sA[tid*64 + n];
                    if (v > bv) { bv = v; bi = n; }
                }
                g_actidx[m0 + tid] = bi;
            }
            __syncthreads();
        }
        grid_sync();

        // ---- P4: r-cell + t-cell ----
        for (int w = gthr; w < 2*B_*CF_; w += nthr) {
            if (w < B_*CF_) {
                int idx = w, m = idx >> 10, j = idx & 1023;
                float4 g4 = ((const float4*)g_GR)[idx];
                float4 p4 = ((const float4*)g_Pr)[idx];
                float4 wa = ((const float4*)g_WaR)[(size_t)g_actidx[m] * CF_ + j];
                float4 wr = ((const float4*)g_WrR)[(size_t)g_residx[m] * CF_ + j];
                float gi = g4.x + p4.x + wa.x + wr.x;
                float gf = g4.y + p4.y + wa.y + wr.y;
                float gg = g4.z + p4.z + wa.z + wr.z;
                float go = g4.w + p4.w + wa.w + wr.w;
                float cn = sigm(gf) * g_cR[idx] + sigm(gi) * tanhf(gg);
                g_cR[idx] = cn;
                float hv = sigm(go) * tanhf(cn);
                g_hR[idx] = hv;
                store_Asplit(g_AhR, g_AlR, m, j, hv);
            } else {
                int idx = w - B_*CF_, m = idx >> 10, j = idx & 1023;
                float4 g4 = ((const float4*)g_GT)[idx];
                float4 p4 = ((const float4*)g_Pt)[idx];
                float4 wa = ((const float4*)g_WaT)[(size_t)g_actidx[m] * CF_ + j];
                float4 wt = ((const float4*)g_WtT)[j];
                float tv = g_tsv[m];
                float gi = g4.x + p4.x + wa.x + tv * wt.x;
                float gf = g4.y + p4.y + wa.y + tv * wt.y;
                float gg = g4.z + p4.z + wa.z + tv * wt.z;
                float go = g4.w + p4.w + wa.w + tv * wt.w;
                float cn = sigm(gf) * g_cT[idx] + sigm(gi) * tanhf(gg);
                g_cT[idx] = cn;
                float hv = sigm(go) * tanhf(cn);
                store_Asplit(g_AhT, g_AlT, m, j, hv);
            }
        }
        grid_sync();

        // ---- P5: one exact wave of 152 items:
        //      32 ts-hidden(t) + 64 res-head(t) + 56 a-tiles of step t+1 ----
        int nP5 = (t < T_ - 1) ? 152 : 96;
        for (int blk = bid; blk < nP5; blk += nb) {
            if (blk < 32) {
                int tm = blk >> 2, tn = blk & 3;
                mma_direct(g_AhT, g_AlT, g_Bw1c, tm, tn, 1,
                           g_hidden, e2ts_b1,
                           nullptr, nullptr, nullptr, nullptr, nullptr,
                           nullptr, nullptr);
            } else if (blk < 96) {
                int m0 = (blk - 32) * 16;
                float acc4[4] = {0.f, 0.f, 0.f, 0.f};
                const float* h = g_hR;
                const int rr = tid >> 5, cc0 = (tid & 31) * 4;
                for (int kb = 0; kb < CF_; kb += 32) {
                    if (tid < 128) {
                        int r = tid >> 3, c4 = (tid & 7) * 4;
                        float4 v = *(const float4*)&h[(size_t)(m0 + r) * CF_ + kb + c4];
                        sA[r*32 + c4+0] = v.x; sA[r*32 + c4+1] = v.y;
                        sA[r*32 + c4+2] = v.z; sA[r*32 + c4+3] = v.w;
                    }
                    #pragma unroll
                    for (int qq = 0; qq < 2; qq++) {
                        int idx = tid * 2 + qq;            // 1024 float4s
                        int ccw = idx >> 3, k4 = (idx & 7) * 4;
                        float4 v = *(const float4*)&e2res_w[(size_t)ccw * CF_ + kb + k4];
                        sB[(k4+0)*128 + ccw] = v.x; sB[(k4+1)*128 + ccw] = v.y;
                        sB[(k4+2)*128 + ccw] = v.z; sB[(k4+3)*128 + ccw] = v.w;
                    }
                    __syncthreads();
                    #pragma unroll
                    for (int k = 0; k < 32; k++) {
                        float a = sA[rr*32 + k];
                        acc4[0] += a * sB[k*128 + cc0];
                        acc4[1] += a * sB[k*128 + cc0 + 1];
                        acc4[2] += a * sB[k*128 + cc0 + 2];
                        acc4[3] += a * sB[k*128 + cc0 + 3];
                    }
                    __syncthreads();
                }
                #pragma unroll
                for (int j = 0; j < 4; j++) {
                    float v = acc4[j] + e2res_b[cc0 + j];
                    sA[rr*128 + cc0 + j] = v;
                    out[RESS_BASE + (size_t)(m0 + rr) * (T_*R_) + t*R_ + cc0 + j] = v;
                }
                __syncthreads();
                if (tid < 16) {
                    float bv = -INFINITY; int bi = 0;
                    for (int n = 0; n < R_; n++) {
                        float v = sA[tid*128 + n];
                        if (v > bv) { bv = v; bi = n; }
                    }
                    g_residx[m0 + tid] = bi;
                }
                __syncthreads();
            } else {
                // a-tiles 200..255 of step t+1 (reads actidx(t), AhA[p(t+1)])
                int idx = 200 + (blk - 96);
                int tm = idx & 7, tn = idx >> 3;
                int p2 = (t + 1) & 1, q2 = p2 ^ 1;
                mma_direct(g_AhA[p2], g_AlA[p2], g_BcA, tm, tn, 2,
                           nullptr, nullptr,
                           g_Pa, g_WaA, g_actidx, g_cA, g_hA,
                           g_AhA[q2], g_AlA[q2]);
            }
        }
        grid_sync();
    }

    // ================= epilogue: ts-dot for t=63 + final softmaxes ============
    for (int m = bid * 16 + wid; m < B_; m += nb * 16) {
        const float* hrow = &g_hidden[(size_t)m * (CF_/2)];
        float s = 0.f;
        for (int j = lane; j < CF_/2; j += 32) s += hrow[j] * e2ts_w2[j];
        #pragma unroll
        for (int off = 16; off; off >>= 1)
            s += __shfl_down_sync(0xffffffffu, s, off);
        if (lane == 0)
            out[TS_BASE + (size_t)m * T_ + (T_ - 1)] = s + e2ts_b2[0];
    }
    for (int r = bid * 16 + wid; r < B_*T_; r += nb * 16) {    // acts, W=64
        float* row = out + (size_t)r * A_;
        float v0 = row[lane], v1 = row[lane + 32];
        float mx = fmaxf(v0, v1);
        #pragma unroll
        for (int off = 16; off; off >>= 1)
            mx = fmaxf(mx, __shfl_xor_sync(0xffffffffu, mx, off));
        float e0 = expf(v0 - mx), e1 = expf(v1 - mx);
        float s = e0 + e1;
        #pragma unroll
        for (int off = 16; off; off >>= 1)
            s += __shfl_xor_sync(0xffffffffu, s, off);
        float inv = 1.f / s;
        row[lane] = e0 * inv; row[lane + 32] = e1 * inv;
    }
    for (int r = bid * 16 + wid; r < B_*T_; r += nb * 16) {    // ress, W=128
        float* row = out + RESS_BASE + (size_t)r * R_;
        float v[4];
        float mx = -INFINITY;
        #pragma unroll
        for (int u = 0; u < 4; u++) { v[u] = row[lane + u*32]; mx = fmaxf(mx, v[u]); }
        #pragma unroll
        for (int off = 16; off; off >>= 1)
            mx = fmaxf(mx, __shfl_xor_sync(0xffffffffu, mx, off));
        float e[4]; float s = 0.f;
        #pragma unroll
        for (int u = 0; u < 4; u++) { e[u] = expf(v[u] - mx); s += e[u]; }
        #pragma unroll
        for (int off = 16; off; off >>= 1)
            s += __shfl_xor_sync(0xffffffffu, s, off);
        float inv = 1.f / s;
        #pragma unroll
        for (int u = 0; u < 4; u++) row[lane + u*32] = e[u] * inv;
    }
}

// ---------------- host -------------------------------------------------------
extern "C" void kernel_launch(void* const* d_in, const int* in_sizes, int n_in,
                              void* d_out, int out_size)
{
    const float* z        = (const float*)d_in[0];
    const float* z2t_w    = (const float*)d_in[1];
    const float* z2t_b    = (const float*)d_in[2];
    const float* Wih_a    = (const float*)d_in[3];
    const float* Whh_a    = (const float*)d_in[4];
    const float* b_a      = (const float*)d_in[5];
    const float* Wih_r    = (const float*)d_in[6];
    const float* Whh_r    = (const float*)d_in[7];
    const float* b_r      = (const float*)d_in[8];
    const float* Wih_t    = (const float*)d_in[9];
    const float* Whh_t    = (const float*)d_in[10];
    const float* b_t      = (const float*)d_in[11];
    const float* e2act_w  = (const float*)d_in[12];
    const float* e2act_b  = (const float*)d_in[13];
    const float* e2res_w  = (const float*)d_in[14];
    const float* e2res_b  = (const float*)d_in[15];
    const float* e2ts_w1  = (const float*)d_in[16];
    const float* e2ts_b1  = (const float*)d_in[17];
    const float* e2ts_w2  = (const float*)d_in[18];
    const float* e2ts_b2  = (const float*)d_in[19];
    float* out = (float*)d_out;

    int dev = 0;
    cudaGetDevice(&dev);
    int nsm = 0;
    cudaDeviceGetAttribute(&nsm, cudaDevAttrMultiProcessorCount, dev);
    int occ = 0;
    cudaOccupancyMaxActiveBlocksPerMultiprocessor(&occ, decoder_all, NT, 0);
    if (occ < 1) occ = 1;
    if (nsm < 1) nsm = 1;
    int nb = nsm * occ;

    decoder_all<<<nb, NT>>>(
        z, z2t_w, z2t_b,
        Wih_a, Whh_a, b_a,
        Wih_r, Whh_r, b_r,
        Wih_t, Whh_t, b_t,
        e2act_w, e2act_b, e2res_w, e2res_b,
        e2ts_w1, e2ts_b1, e2ts_w2, e2ts_b2,
        out);
}